// round 17
// baseline (speedup 1.0000x reference)
#include <cuda_runtime.h>
#include <cuda_bf16.h>
#include <cstdint>

// Depth-to-space, SCALE=2 — Blackwell 256-bit ld/st variant (final lever).
// in : [B=16, H=128, W=128, C=256] fp32
// out: [B, 2H=256, 2W=256, C/4=64] fp32
// out[b, 2h+j, 2w+k, c] = in[b, h, w, 4c + 2k + j]
//
// Each thread: 32 consecutive input floats (4x ld.global.v8.f32 = 128B
// contiguous, 4KB/warp/instr), register transpose, 4x st.global.v8.f32
// (out channels 8g..8g+7 at each (j,k) position; 8 lanes form 256B
// contiguous runs). Halves LDG/STG instruction count and L1tex wavefront
// count vs the 128-bit kernel; DRAM traffic identical (536MB, minimal).

__device__ __forceinline__ void ldg_v8(const float* p, float* r)
{
    asm volatile("ld.global.nc.v8.f32 {%0,%1,%2,%3,%4,%5,%6,%7}, [%8];"
                 : "=f"(r[0]), "=f"(r[1]), "=f"(r[2]), "=f"(r[3]),
                   "=f"(r[4]), "=f"(r[5]), "=f"(r[6]), "=f"(r[7])
                 : "l"(p));
}

__device__ __forceinline__ void stg_v8(float* p, const float* r)
{
    asm volatile("st.global.v8.f32 [%0], {%1,%2,%3,%4,%5,%6,%7,%8};"
                 :: "l"(p),
                    "f"(r[0]), "f"(r[1]), "f"(r[2]), "f"(r[3]),
                    "f"(r[4]), "f"(r[5]), "f"(r[6]), "f"(r[7])
                 : "memory");
}

__global__ void __launch_bounds__(256, 6)
d2s_kernel(const float* __restrict__ in, float* __restrict__ out)
{
    // 16*128*128 pixels * 8 groups = 2,097,152 threads
    unsigned idx = blockIdx.x * 256u + threadIdx.x;

    unsigned g     = idx & 7u;           // out channel group: 8g..8g+7
    unsigned pixel = idx >> 3;           // b*H*W + h*W + w
    unsigned w     = pixel & 127u;
    unsigned h     = (pixel >> 7) & 127u;
    unsigned b     = pixel >> 14;

    // 32 consecutive input floats: channels 32g..32g+31 of this pixel.
    // Front-batched: 4x 256-bit loads, 128B contiguous per thread.
    const float* base = in + ((size_t)idx << 5);
    float r[32];
    ldg_v8(base +  0, r +  0);
    ldg_v8(base +  8, r +  8);
    ldg_v8(base + 16, r + 16);
    ldg_v8(base + 24, r + 24);

    // Transpose: input channel 32g + 4m + (2k+j)  (m = 0..7) is output
    // channel 8g+m at position (j,k).  Gather component (2k+j) of each
    // float4 m into an 8-wide store vector per (j,k).
    float s00[8], s10[8], s01[8], s11[8];
#pragma unroll
    for (int m = 0; m < 8; ++m) {
        s00[m] = r[4*m + 0];   // j=0,k=0
        s10[m] = r[4*m + 1];   // j=1,k=0
        s01[m] = r[4*m + 2];   // j=0,k=1
        s11[m] = r[4*m + 3];   // j=1,k=1
    }

    // Output offsets in float units:
    // o(j,k) = ((r0+j)*256 + 2w+k)*64 + 8g
    //        = ((r0+j)<<14) + ((2w+k)<<6) + (g<<3)
    unsigned r0  = (b << 8) + (h << 1);            // output row for j=0
    unsigned o00 = (r0 << 14) + (w << 7) + (g << 3);
    unsigned o10 = o00 + (1u << 14);               // +1 output row (j=1)
    unsigned o01 = o00 + 64u;                      // +1 output col (k=1)
    unsigned o11 = o10 + 64u;

    stg_v8(out + o00, s00);
    stg_v8(out + o10, s10);
    stg_v8(out + o01, s01);
    stg_v8(out + o11, s11);
}

extern "C" void kernel_launch(void* const* d_in, const int* in_sizes, int n_in,
                              void* d_out, int out_size)
{
    const float* in = (const float*)d_in[0];
    float* out = (float*)d_out;

    // total threads = in_sizes[0] / 32 = 2,097,152
    unsigned n_threads = (unsigned)(in_sizes[0] / 32);
    unsigned n_blocks  = (n_threads + 255u) / 256u;   // 8192

    d2s_kernel<<<n_blocks, 256>>>(in, out);
}